// round 7
// baseline (speedup 1.0000x reference)
#include <cuda_runtime.h>

#define BATCH   4096
#define HALF    2048       // batch columns per pass (state footprint 42 MB < L2)
#define IN_W    1024
#define DEPTH   8
#define BLOCKS  64
#define NACT    8
#define GROW    512
#define TOTAL   5120
#define OUT_W   512

// 84 MB scratch state (static __device__ global: allowed, no runtime alloc)
__device__ float g_data[(size_t)TOTAL * BATCH];

typedef unsigned long long ull;

// Pre-packed rotation constants: g_cs[(m*64+blk)*64 + L*8 + a] = ((c,c),(s,s))
__device__ ulonglong2 g_cs[DEPTH * BLOCKS * 64];

__device__ __forceinline__ ull pk2(float x, float y) {
    ull r; asm("mov.b64 %0, {%1, %2};" : "=l"(r) : "f"(x), "f"(y)); return r;
}
__device__ __forceinline__ void upk2(ull v, float& x, float& y) {
    asm("mov.b64 {%0, %1}, %2;" : "=f"(x), "=f"(y) : "l"(v));
}
// Packed f32x2 FMA/MUL — Blackwell FFMA2 path (PTX-only)
__device__ __forceinline__ ull fma2(ull a, ull b, ull c) {
    ull d; asm("fma.rn.f32x2 %0, %1, %2, %3;" : "=l"(d) : "l"(a), "l"(b), "l"(c)); return d;
}
__device__ __forceinline__ ull mul2(ull a, ull b) {
    ull d; asm("mul.rn.f32x2 %0, %1, %2;" : "=l"(d) : "l"(a), "l"(b)); return d;
}
__device__ __forceinline__ float sqrt_ap(float x) {
    float r; asm("sqrt.approx.f32 %0, %1;" : "=f"(r) : "f"(x)); return r;
}
__device__ __forceinline__ float actf(float p) {
    return 0.5f * (p + sqrt_ap(fmaf(p, p, 1.0f)));
}
// evict_last access policy (createpolicy + cache_hint: works at any width)
__device__ __forceinline__ ull mk_policy() {
    ull pol;
    asm("createpolicy.fractional.L2::evict_last.b64 %0, 1.0;" : "=l"(pol));
    return pol;
}
__device__ __forceinline__ ull ldg_el(const float* p, ull pol) {
    ull v;
    asm("ld.global.L2::cache_hint.b64 %0, [%1], %2;"
        : "=l"(v) : "l"(p), "l"(pol));
    return v;
}
__device__ __forceinline__ void stg_el(float* p, ull v, ull pol) {
    asm volatile("st.global.L2::cache_hint.b64 [%0], %1, %2;"
                 :: "l"(p), "l"(v), "l"(pol));
}
// d_out: streaming store (read-never)
__device__ __forceinline__ void stg_cs(float* p, ull v) {
    asm volatile("st.global.cs.b64 [%0], %1;" :: "l"(p), "l"(v));
}

// ---------------------------------------------------------------------------
// One-time: pack trig table. angles: [DEPTH][8][512], 512 = blk*8 + a
// ---------------------------------------------------------------------------
__global__ void trig_kernel(const float* __restrict__ angles) {
    int i = blockIdx.x * blockDim.x + threadIdx.x;
    if (i >= DEPTH * 8 * 512) return;
    int m = i / 4096, r = i % 4096;
    int L = r / 512,  q = r % 512;
    int blk = q / 8,  a = q % 8;
    float sn, cs;
    sincosf(angles[i], &sn, &cs);
    g_cs[(m * BLOCKS + blk) * 64 + L * 8 + a] =
        make_ulonglong2(pk2(cs, cs), pk2(sn, sn));
}

// ---------------------------------------------------------------------------
// One butterfly module on one batch half. CUDA block = (blk) x (256 cols).
// Thread owns 2 batch columns of all 16 rows as f32x2; transform in registers.
// MODE: 0 = middle, 1 = first (gather from input*scales), 2 = last (act->out)
// ---------------------------------------------------------------------------
template<int MODE>
__global__ __launch_bounds__(128, 6)
void module_kernel(const float* __restrict__ biases,  // [512] this module
                   const int*   __restrict__ idx,     // [1024] this module
                   int mod,
                   int cbase,                         // batch column base
                   const float* __restrict__ input,   // (1024,4096) for FIRST
                   const float* __restrict__ scales,  // (1024,)     for FIRST
                   float* __restrict__ out_ext)       // d_out for LAST
{
    const int blk = blockIdx.y;
    const int tid = threadIdx.x;

    __shared__ int   s_idx[16];
    __shared__ ull   s_scl[16];
    __shared__ float s_bias[NACT];
    __shared__ __align__(16) ulonglong2 s_cs[64];

    if (tid < 16) {
        int row = idx[blk * 16 + tid];
        s_idx[tid] = row;
        if (MODE == 1) { float s = scales[row]; s_scl[tid] = pk2(s, s); }
    }
    if (tid < 8)  s_bias[tid] = biases[blk * 8 + tid];
    if (tid < 64) s_cs[tid] = g_cs[(mod * BLOCKS + blk) * 64 + tid];
    __syncthreads();

    const int b = cbase + (blockIdx.x * 128 + tid) * 2;  // first of 2 cols
    const ull SGN = 0x8000000080000000ULL;
    const ull pol = mk_policy();

    // Gather 16 rows (16 independent LDG.64 -> MLP=16)
    ull v[16];
    #pragma unroll
    for (int j = 0; j < 16; j++) {
        if (MODE == 1)
            v[j] = *(const ull*)(input + (size_t)s_idx[j] * BATCH + b);
        else
            v[j] = ldg_el(g_data + (size_t)s_idx[j] * BATCH + b, pol);
    }
    if (MODE == 1) {
        #pragma unroll
        for (int j = 0; j < 16; j++) v[j] = mul2(v[j], s_scl[j]);
    }

    // 4 IN rotation layers (strides 1,2,4,8), all in registers
    #pragma unroll
    for (int k = 0; k < 4; k++) {
        const int st = 1 << k;
        #pragma unroll
        for (int g = 0; g < 16; g += 2 * st) {
            #pragma unroll
            for (int j = 0; j < st; j++) {
                const int lo = g + j, hi = lo + st;
                const ulonglong2 cs = s_cs[k * 8 + (g >> 1) + j];  // LDS.128
                const ull ns = cs.y ^ SGN;                         // -s on ALU
                ull xl = v[lo], xh = v[hi];
                v[lo] = fma2(cs.x, xl, mul2(cs.y, xh));
                v[hi] = fma2(ns,   xl, mul2(cs.x, xh));
            }
        }
    }

    // Activation on rows 0..7; write act rows (d_out for last module)
    #pragma unroll
    for (int u = 0; u < NACT; u++) {
        const float bb = s_bias[u];
        float x0, x1;
        upk2(v[u], x0, x1);
        x0 = actf(x0 + bb); x1 = actf(x1 + bb);
        v[u] = pk2(x0, x1);
        if (MODE == 2)
            stg_cs(out_ext + (size_t)(blk * NACT + u) * BATCH + b, v[u]);
        else
            stg_el(g_data + (size_t)(IN_W + GROW * mod + blk * NACT + u) * BATCH + b,
                   v[u], pol);
    }

    if (MODE != 2) {
        // 4 OUT rotation layers (trig layers 4..7, strides 1,2,4,8)
        #pragma unroll
        for (int k = 0; k < 4; k++) {
            const int st = 1 << k;
            #pragma unroll
            for (int g = 0; g < 16; g += 2 * st) {
                #pragma unroll
                for (int j = 0; j < st; j++) {
                    const int lo = g + j, hi = lo + st;
                    const ulonglong2 cs = s_cs[(4 + k) * 8 + (g >> 1) + j];
                    const ull ns = cs.y ^ SGN;
                    ull xl = v[lo], xh = v[hi];
                    v[lo] = fma2(cs.x, xl, mul2(cs.y, xh));
                    v[hi] = fma2(ns,   xl, mul2(cs.x, xh));
                }
            }
        }
        // Scatter back (16 independent STG.64, pinned in L2)
        #pragma unroll
        for (int j = 0; j < 16; j++)
            stg_el(g_data + (size_t)s_idx[j] * BATCH + b, v[j], pol);
    }
}

// ---------------------------------------------------------------------------
extern "C" void kernel_launch(void* const* d_in, const int* in_sizes, int n_in,
                              void* d_out, int out_size) {
    const float* input   = (const float*)d_in[0];   // (1024, 4096)
    const float* scales  = (const float*)d_in[1];   // (1024,)
    const float* angles  = (const float*)d_in[2];   // (8, 8, 512)
    const float* biases  = (const float*)d_in[3];   // (8, 512)
    const int*   indices = (const int*)d_in[4];     // (8, 1024)
    float* out = (float*)d_out;                     // (512, 4096)

    const int nt = DEPTH * 8 * 512;
    trig_kernel<<<(nt + 255) / 256, 256>>>(angles);

    dim3 grid(HALF / (128 * 2), BLOCKS);   // (8, 64) = 512 CTAs, one wave
    for (int h = 0; h < BATCH / HALF; h++) {
        const int cbase = h * HALF;
        for (int m = 0; m < DEPTH; m++) {
            const float* bia = biases + (size_t)m * 512;
            const int*   ix  = indices + (size_t)m * 1024;
            if (m == 0)
                module_kernel<1><<<grid, 128>>>(bia, ix, m, cbase,
                                                input, scales, nullptr);
            else if (m < DEPTH - 1)
                module_kernel<0><<<grid, 128>>>(bia, ix, m, cbase,
                                                nullptr, nullptr, nullptr);
            else
                module_kernel<2><<<grid, 128>>>(bia, ix, m, cbase,
                                                nullptr, nullptr, out);
        }
    }
}

// round 8
// speedup vs baseline: 1.0626x; 1.0626x over previous
#include <cuda_runtime.h>

#define BATCH   4096
#define IN_W    1024
#define DEPTH   8
#define BLOCKS  64
#define NACT    8
#define GROW    512
#define TOTAL   5120
#define OUT_W   512
#define NCTA    1024       // 64 blks x 16 col-groups; one unit per CTA per module

// 84 MB scratch state (static __device__ global: allowed, no runtime alloc)
__device__ float g_data[(size_t)TOTAL * BATCH];

typedef unsigned long long ull;

// Pre-packed rotation constants: g_cs[(m*64+blk)*64 + L*8 + a] = ((c,c),(s,s))
__device__ ulonglong2 g_cs[DEPTH * BLOCKS * 64];

// Grid barrier state
__device__ unsigned g_bar_cnt = 0;
__device__ volatile unsigned g_bar_gen = 0;

__device__ __forceinline__ ull pk2(float x, float y) {
    ull r; asm("mov.b64 %0, {%1, %2};" : "=l"(r) : "f"(x), "f"(y)); return r;
}
__device__ __forceinline__ void upk2(ull v, float& x, float& y) {
    asm("mov.b64 {%0, %1}, %2;" : "=f"(x), "=f"(y) : "l"(v));
}
// Packed f32x2 FMA/MUL — Blackwell FFMA2 path (PTX-only)
__device__ __forceinline__ ull fma2(ull a, ull b, ull c) {
    ull d; asm("fma.rn.f32x2 %0, %1, %2, %3;" : "=l"(d) : "l"(a), "l"(b), "l"(c)); return d;
}
__device__ __forceinline__ ull mul2(ull a, ull b) {
    ull d; asm("mul.rn.f32x2 %0, %1, %2;" : "=l"(d) : "l"(a), "l"(b)); return d;
}
__device__ __forceinline__ float sqrt_ap(float x) {
    float r; asm("sqrt.approx.f32 %0, %1;" : "=f"(r) : "f"(x)); return r;
}
__device__ __forceinline__ float actf(float p) {
    return 0.5f * (p + sqrt_ap(fmaf(p, p, 1.0f)));
}
__device__ __forceinline__ ull mk_policy() {
    ull pol;
    asm("createpolicy.fractional.L2::evict_last.b64 %0, 1.0;" : "=l"(pol));
    return pol;
}
__device__ __forceinline__ ull ldg_el(const float* p, ull pol) {
    ull v;
    asm("ld.global.L2::cache_hint.b64 %0, [%1], %2;"
        : "=l"(v) : "l"(p), "l"(pol));
    return v;
}
__device__ __forceinline__ void stg_el(float* p, ull v, ull pol) {
    asm volatile("st.global.L2::cache_hint.b64 [%0], %1, %2;"
                 :: "l"(p), "l"(v), "l"(pol));
}
__device__ __forceinline__ void stg_cs(float* p, ull v) {
    asm volatile("st.global.cs.b64 [%0], %1;" :: "l"(p), "l"(v));
}

// Sense-reversing grid barrier. Only executed when all NCTA CTAs co-resident.
__device__ __forceinline__ void grid_barrier() {
    __syncthreads();
    if (threadIdx.x == 0) {
        unsigned gen = g_bar_gen;
        __threadfence();
        if (atomicAdd(&g_bar_cnt, 1u) == NCTA - 1) {
            g_bar_cnt = 0;
            __threadfence();
            g_bar_gen = gen + 1;
        } else {
            while (g_bar_gen == gen) { __nanosleep(64); }
        }
        __threadfence();
    }
    __syncthreads();
}

// ---------------------------------------------------------------------------
// One-time: pack trig table. angles: [DEPTH][8][512], 512 = blk*8 + a
// ---------------------------------------------------------------------------
__global__ void trig_kernel(const float* __restrict__ angles) {
    int i = blockIdx.x * blockDim.x + threadIdx.x;
    if (i >= DEPTH * 8 * 512) return;
    int m = i / 4096, r = i % 4096;
    int L = r / 512,  q = r % 512;
    int blk = q / 8,  a = q % 8;
    float sn, cs;
    sincosf(angles[i], &sn, &cs);
    g_cs[(m * BLOCKS + blk) * 64 + L * 8 + a] =
        make_ulonglong2(pk2(cs, cs), pk2(sn, sn));
}

// ---------------------------------------------------------------------------
// Persistent network kernel: CTA = (butterfly blk, col-group of 256 cols).
// Runs modules [mStart, mEnd); grid barrier between modules (only when the
// range has >1 module — the fallback path launches one module per kernel,
// so the barrier never executes without co-residency).
// ---------------------------------------------------------------------------
__global__ __launch_bounds__(128, 7)
void net_kernel(const float* __restrict__ biases,   // [DEPTH][512]
                const int*   __restrict__ indices,  // [DEPTH][1024]
                const float* __restrict__ input,    // (1024, 4096)
                const float* __restrict__ scales,   // (1024,)
                float* __restrict__ out,            // (512, 4096)
                int mStart, int mEnd)
{
    const int unit = blockIdx.x;
    const int blk  = unit >> 4;          // 0..63
    const int cg   = unit & 15;          // 0..15
    const int tid  = threadIdx.x;
    const int b    = (cg * 128 + tid) * 2;   // first of 2 batch cols

    __shared__ int   s_idx[16];
    __shared__ ull   s_scl[16];
    __shared__ float s_bias[NACT];
    __shared__ __align__(16) ulonglong2 s_cs[64];

    const ull SGN = 0x8000000080000000ULL;
    const ull pol = mk_policy();

    for (int m = mStart; m < mEnd; m++) {
        const bool first = (m == 0);
        const bool last  = (m == DEPTH - 1);

        if (tid < 16) {
            int row = indices[m * 1024 + blk * 16 + tid];
            s_idx[tid] = row;
            if (first) { float s = scales[row]; s_scl[tid] = pk2(s, s); }
        }
        if (tid < 8)  s_bias[tid] = biases[m * GROW + blk * 8 + tid];
        if (tid < 64) s_cs[tid] = g_cs[(m * BLOCKS + blk) * 64 + tid];
        __syncthreads();

        // Gather 16 rows (16 independent LDG.64 -> MLP=16)
        ull v[16];
        #pragma unroll
        for (int j = 0; j < 16; j++) {
            if (first)
                v[j] = *(const ull*)(input + (size_t)s_idx[j] * BATCH + b);
            else
                v[j] = ldg_el(g_data + (size_t)s_idx[j] * BATCH + b, pol);
        }
        if (first) {
            #pragma unroll
            for (int j = 0; j < 16; j++) v[j] = mul2(v[j], s_scl[j]);
        }

        // 4 IN rotation layers (strides 1,2,4,8), all in registers
        #pragma unroll
        for (int k = 0; k < 4; k++) {
            const int st = 1 << k;
            #pragma unroll
            for (int g = 0; g < 16; g += 2 * st) {
                #pragma unroll
                for (int j = 0; j < st; j++) {
                    const int lo = g + j, hi = lo + st;
                    const ulonglong2 cs = s_cs[k * 8 + (g >> 1) + j];
                    const ull ns = cs.y ^ SGN;
                    ull xl = v[lo], xh = v[hi];
                    v[lo] = fma2(cs.x, xl, mul2(cs.y, xh));
                    v[hi] = fma2(ns,   xl, mul2(cs.x, xh));
                }
            }
        }

        // Activation on rows 0..7; write act rows (d_out for last module)
        #pragma unroll
        for (int u = 0; u < NACT; u++) {
            const float bb = s_bias[u];
            float x0, x1;
            upk2(v[u], x0, x1);
            x0 = actf(x0 + bb); x1 = actf(x1 + bb);
            v[u] = pk2(x0, x1);
            if (last)
                stg_cs(out + (size_t)(blk * NACT + u) * BATCH + b, v[u]);
            else
                stg_el(g_data + (size_t)(IN_W + GROW * m + blk * NACT + u) * BATCH + b,
                       v[u], pol);
        }

        if (!last) {
            // 4 OUT rotation layers (trig layers 4..7, strides 1,2,4,8)
            #pragma unroll
            for (int k = 0; k < 4; k++) {
                const int st = 1 << k;
                #pragma unroll
                for (int g = 0; g < 16; g += 2 * st) {
                    #pragma unroll
                    for (int j = 0; j < st; j++) {
                        const int lo = g + j, hi = lo + st;
                        const ulonglong2 cs = s_cs[(4 + k) * 8 + (g >> 1) + j];
                        const ull ns = cs.y ^ SGN;
                        ull xl = v[lo], xh = v[hi];
                        v[lo] = fma2(cs.x, xl, mul2(cs.y, xh));
                        v[hi] = fma2(ns,   xl, mul2(cs.x, xh));
                    }
                }
            }
            // Scatter back (16 independent STG.64)
            #pragma unroll
            for (int j = 0; j < 16; j++)
                stg_el(g_data + (size_t)s_idx[j] * BATCH + b, v[j], pol);
        }

        if (m + 1 < mEnd) grid_barrier();
    }
}

// ---------------------------------------------------------------------------
extern "C" void kernel_launch(void* const* d_in, const int* in_sizes, int n_in,
                              void* d_out, int out_size) {
    const float* input   = (const float*)d_in[0];   // (1024, 4096)
    const float* scales  = (const float*)d_in[1];   // (1024,)
    const float* angles  = (const float*)d_in[2];   // (8, 8, 512)
    const float* biases  = (const float*)d_in[3];   // (8, 512)
    const int*   indices = (const int*)d_in[4];     // (8, 1024)
    float* out = (float*)d_out;                     // (512, 4096)

    const int nt = DEPTH * 8 * 512;
    trig_kernel<<<(nt + 255) / 256, 256>>>(angles);

    // Persistent path requires all NCTA CTAs co-resident (for the barrier).
    int dev = 0;
    cudaGetDevice(&dev);
    int nsm = 0;
    cudaDeviceGetAttribute(&nsm, cudaDevAttrMultiProcessorCount, dev);
    int occ = 0;
    cudaOccupancyMaxActiveBlocksPerMultiprocessor(&occ, net_kernel, 128, 0);

    if (occ * nsm >= NCTA) {
        net_kernel<<<NCTA, 128>>>(biases, indices, input, scales, out, 0, DEPTH);
    } else {
        for (int m = 0; m < DEPTH; m++)
            net_kernel<<<NCTA, 128>>>(biases, indices, input, scales, out, m, m + 1);
    }
}

// round 9
// speedup vs baseline: 1.0835x; 1.0197x over previous
#include <cuda_runtime.h>

#define BATCH   4096
#define IN_W    1024
#define DEPTH   8
#define BLOCKS  64
#define NACT    8
#define GROW    512
#define TOTAL   5120
#define OUT_W   512
#define NCTA    1024       // 64 blks x 16 col-groups
#define NCG     16         // independent column-slice pipelines
#define CPG     64         // CTAs per col-group

// 84 MB scratch state (static __device__ global: allowed, no runtime alloc)
__device__ float g_data[(size_t)TOTAL * BATCH];

typedef unsigned long long ull;

// Pre-packed rotation constants: g_cs[(m*64+blk)*64 + L*8 + a] = ((c,c),(s,s))
__device__ ulonglong2 g_cs[DEPTH * BLOCKS * 64];

// Dead-write masks: alive_sc[m][i] = row idx[m][i] is read by a later module;
// alive_act[m][u] = act row IN_W+512m+u is read by a later module. (m = 0..6)
__device__ unsigned char g_alive_sc[DEPTH - 1][1024];
__device__ unsigned char g_alive_act[DEPTH - 1][512];

// Per-col-group barrier state (16 independent 64-CTA barriers)
__device__ unsigned g_cnt[NCG];
__device__ volatile unsigned g_gen[NCG];

__device__ __forceinline__ ull pk2(float x, float y) {
    ull r; asm("mov.b64 %0, {%1, %2};" : "=l"(r) : "f"(x), "f"(y)); return r;
}
__device__ __forceinline__ void upk2(ull v, float& x, float& y) {
    asm("mov.b64 {%0, %1}, %2;" : "=f"(x), "=f"(y) : "l"(v));
}
// Packed f32x2 FMA/MUL — Blackwell FFMA2 path (PTX-only)
__device__ __forceinline__ ull fma2(ull a, ull b, ull c) {
    ull d; asm("fma.rn.f32x2 %0, %1, %2, %3;" : "=l"(d) : "l"(a), "l"(b), "l"(c)); return d;
}
__device__ __forceinline__ ull mul2(ull a, ull b) {
    ull d; asm("mul.rn.f32x2 %0, %1, %2;" : "=l"(d) : "l"(a), "l"(b)); return d;
}
__device__ __forceinline__ float sqrt_ap(float x) {
    float r; asm("sqrt.approx.f32 %0, %1;" : "=f"(r) : "f"(x)); return r;
}
__device__ __forceinline__ float actf(float p) {
    return 0.5f * (p + sqrt_ap(fmaf(p, p, 1.0f)));
}
__device__ __forceinline__ ull mk_policy() {
    ull pol;
    asm("createpolicy.fractional.L2::evict_last.b64 %0, 1.0;" : "=l"(pol));
    return pol;
}
__device__ __forceinline__ ull ldg_el(const float* p, ull pol) {
    ull v;
    asm("ld.global.L2::cache_hint.b64 %0, [%1], %2;"
        : "=l"(v) : "l"(p), "l"(pol));
    return v;
}
__device__ __forceinline__ void stg_el(float* p, ull v, ull pol) {
    asm volatile("st.global.L2::cache_hint.b64 [%0], %1, %2;"
                 :: "l"(p), "l"(v), "l"(pol));
}
__device__ __forceinline__ void stg_cs(float* p, ull v) {
    asm volatile("st.global.cs.b64 [%0], %1;" :: "l"(p), "l"(v));
}

// Sense-reversing barrier over the 64 CTAs of one column-group.
// Only executed when all NCTA CTAs are co-resident (host-verified).
__device__ __forceinline__ void cg_barrier(int cg) {
    __syncthreads();
    if (threadIdx.x == 0) {
        __threadfence();                       // make our stores visible
        unsigned gen = g_gen[cg];              // read BEFORE arriving
        __threadfence();
        if (atomicAdd(&g_cnt[cg], 1u) == CPG - 1) {
            g_cnt[cg] = 0;
            __threadfence();
            g_gen[cg] = gen + 1;
        } else {
            while (g_gen[cg] == gen) { __nanosleep(32); }
        }
        __threadfence();                       // acquire others' stores
    }
    __syncthreads();
}

// ---------------------------------------------------------------------------
// One-time: pack trig table. angles: [DEPTH][8][512], 512 = blk*8 + a
// ---------------------------------------------------------------------------
__global__ void trig_kernel(const float* __restrict__ angles) {
    int i = blockIdx.x * blockDim.x + threadIdx.x;
    if (i >= DEPTH * 8 * 512) return;
    int m = i / 4096, r = i % 4096;
    int L = r / 512,  q = r % 512;
    int blk = q / 8,  a = q % 8;
    float sn, cs;
    sincosf(angles[i], &sn, &cs);
    g_cs[(m * BLOCKS + blk) * 64 + L * 8 + a] =
        make_ulonglong2(pk2(cs, cs), pk2(sn, sn));
}

// ---------------------------------------------------------------------------
// One-time: dead-write masks via reverse sweep over indices.
// Single CTA of 1024 threads; mark[r]=1 iff row r read by a module > m.
// (Output region rows >= 4608 are never read from g_data: act of the last
//  module goes straight to d_out.)
// ---------------------------------------------------------------------------
__global__ void alive_kernel(const int* __restrict__ indices) {
    __shared__ unsigned char mark[TOTAL];
    const int t = threadIdx.x;
    #pragma unroll
    for (int i = t; i < TOTAL; i += 1024) mark[i] = 0;
    __syncthreads();
    // m = 7: nothing written to g_data; just record its reads.
    mark[indices[7 * 1024 + t]] = 1;
    __syncthreads();
    for (int m = DEPTH - 2; m >= 0; m--) {
        g_alive_sc[m][t] = mark[indices[m * 1024 + t]];
        if (t < 512) g_alive_act[m][t] = mark[IN_W + GROW * m + t];
        __syncthreads();
        if (m > 0) {
            mark[indices[m * 1024 + t]] = 1;
            __syncthreads();
        }
    }
}

// ---------------------------------------------------------------------------
// Persistent network kernel: CTA = (butterfly blk, col-group of 256 cols).
// Runs modules [mStart, mEnd); per-col-group barrier between modules.
// Fallback path launches one module per kernel -> barrier never executes.
// ---------------------------------------------------------------------------
__global__ __launch_bounds__(128, 7)
void net_kernel(const float* __restrict__ biases,   // [DEPTH][512]
                const int*   __restrict__ indices,  // [DEPTH][1024]
                const float* __restrict__ input,    // (1024, 4096)
                const float* __restrict__ scales,   // (1024,)
                float* __restrict__ out,            // (512, 4096)
                int mStart, int mEnd)
{
    const int unit = blockIdx.x;
    const int blk  = unit >> 4;          // 0..63
    const int cg   = unit & 15;          // 0..15
    const int tid  = threadIdx.x;
    const int b    = (cg * 128 + tid) * 2;   // first of 2 batch cols

    __shared__ int   s_idx[16];
    __shared__ ull   s_scl[16];
    __shared__ float s_bias[NACT];
    __shared__ unsigned char s_alsc[16];
    __shared__ unsigned char s_alact[NACT];
    __shared__ __align__(16) ulonglong2 s_cs[64];

    const ull SGN = 0x8000000080000000ULL;
    const ull pol = mk_policy();

    for (int m = mStart; m < mEnd; m++) {
        const bool first = (m == 0);
        const bool last  = (m == DEPTH - 1);

        if (tid < 16) {
            int row = indices[m * 1024 + blk * 16 + tid];
            s_idx[tid]  = row;
            s_alsc[tid] = last ? 0 : g_alive_sc[m][blk * 16 + tid];
            if (first) { float s = scales[row]; s_scl[tid] = pk2(s, s); }
        }
        if (tid < 8) {
            s_bias[tid]  = biases[m * GROW + blk * 8 + tid];
            s_alact[tid] = last ? 1 : g_alive_act[m][blk * NACT + tid];
        }
        if (tid < 64) s_cs[tid] = g_cs[(m * BLOCKS + blk) * 64 + tid];
        __syncthreads();

        // Gather 16 rows (16 independent LDG.64 -> MLP=16)
        ull v[16];
        #pragma unroll
        for (int j = 0; j < 16; j++) {
            if (first)
                v[j] = *(const ull*)(input + (size_t)s_idx[j] * BATCH + b);
            else
                v[j] = ldg_el(g_data + (size_t)s_idx[j] * BATCH + b, pol);
        }
        if (first) {
            #pragma unroll
            for (int j = 0; j < 16; j++) v[j] = mul2(v[j], s_scl[j]);
        }

        // 4 IN rotation layers (strides 1,2,4,8), all in registers
        #pragma unroll
        for (int k = 0; k < 4; k++) {
            const int st = 1 << k;
            #pragma unroll
            for (int g = 0; g < 16; g += 2 * st) {
                #pragma unroll
                for (int j = 0; j < st; j++) {
                    const int lo = g + j, hi = lo + st;
                    const ulonglong2 cs = s_cs[k * 8 + (g >> 1) + j];
                    const ull ns = cs.y ^ SGN;
                    ull xl = v[lo], xh = v[hi];
                    v[lo] = fma2(cs.x, xl, mul2(cs.y, xh));
                    v[hi] = fma2(ns,   xl, mul2(cs.x, xh));
                }
            }
        }

        // Activation on rows 0..7; write live act rows (d_out for last module)
        #pragma unroll
        for (int u = 0; u < NACT; u++) {
            const float bb = s_bias[u];
            float x0, x1;
            upk2(v[u], x0, x1);
            x0 = actf(x0 + bb); x1 = actf(x1 + bb);
            v[u] = pk2(x0, x1);
            if (last)
                stg_cs(out + (size_t)(blk * NACT + u) * BATCH + b, v[u]);
            else if (s_alact[u])
                stg_el(g_data + (size_t)(IN_W + GROW * m + blk * NACT + u) * BATCH + b,
                       v[u], pol);
        }

        if (!last) {
            // 4 OUT rotation layers (trig layers 4..7, strides 1,2,4,8)
            #pragma unroll
            for (int k = 0; k < 4; k++) {
                const int st = 1 << k;
                #pragma unroll
                for (int g = 0; g < 16; g += 2 * st) {
                    #pragma unroll
                    for (int j = 0; j < st; j++) {
                        const int lo = g + j, hi = lo + st;
                        const ulonglong2 cs = s_cs[(4 + k) * 8 + (g >> 1) + j];
                        const ull ns = cs.y ^ SGN;
                        ull xl = v[lo], xh = v[hi];
                        v[lo] = fma2(cs.x, xl, mul2(cs.y, xh));
                        v[hi] = fma2(ns,   xl, mul2(cs.x, xh));
                    }
                }
            }
            // Scatter back only live rows (predicated STG.64)
            #pragma unroll
            for (int j = 0; j < 16; j++)
                if (s_alsc[j])
                    stg_el(g_data + (size_t)s_idx[j] * BATCH + b, v[j], pol);
        }

        if (m + 1 < mEnd) cg_barrier(cg);
    }
}

// ---------------------------------------------------------------------------
extern "C" void kernel_launch(void* const* d_in, const int* in_sizes, int n_in,
                              void* d_out, int out_size) {
    const float* input   = (const float*)d_in[0];   // (1024, 4096)
    const float* scales  = (const float*)d_in[1];   // (1024,)
    const float* angles  = (const float*)d_in[2];   // (8, 8, 512)
    const float* biases  = (const float*)d_in[3];   // (8, 512)
    const int*   indices = (const int*)d_in[4];     // (8, 1024)
    float* out = (float*)d_out;                     // (512, 4096)

    const int nt = DEPTH * 8 * 512;
    trig_kernel<<<(nt + 255) / 256, 256>>>(angles);
    alive_kernel<<<1, 1024>>>(indices);

    // Persistent path requires all NCTA CTAs co-resident (for barriers).
    int dev = 0;
    cudaGetDevice(&dev);
    int nsm = 0;
    cudaDeviceGetAttribute(&nsm, cudaDevAttrMultiProcessorCount, dev);
    int occ = 0;
    cudaOccupancyMaxActiveBlocksPerMultiprocessor(&occ, net_kernel, 128, 0);

    if (occ * nsm >= NCTA) {
        net_kernel<<<NCTA, 128>>>(biases, indices, input, scales, out, 0, DEPTH);
    } else {
        for (int m = 0; m < DEPTH; m++)
            net_kernel<<<NCTA, 128>>>(biases, indices, input, scales, out, m, m + 1);
    }
}

// round 10
// speedup vs baseline: 1.2975x; 1.1975x over previous
#include <cuda_runtime.h>

#define BATCH   4096
#define IN_W    1024
#define DEPTH   8
#define BLOCKS  64
#define NACT    8
#define GROW    512
#define TOTAL   5120
#define OUT_W   512

// 84 MB scratch state (static __device__ global: allowed, no runtime alloc)
__device__ float g_data[(size_t)TOTAL * BATCH];

typedef unsigned long long ull;

// Pre-packed rotation constants: g_cs[(m*64+blk)*64 + L*8 + a] = ((c,c),(s,s))
__device__ ulonglong2 g_cs[DEPTH * BLOCKS * 64];

// Dead-write masks: alive_sc[m][i] = row idx[m][i] is read by a later module;
// alive_act[m][u] = act row IN_W+512m+u is read by a later module. (m = 0..6)
__device__ unsigned char g_alive_sc[DEPTH - 1][1024];
__device__ unsigned char g_alive_act[DEPTH - 1][512];

__device__ __forceinline__ ull pk2(float x, float y) {
    ull r; asm("mov.b64 %0, {%1, %2};" : "=l"(r) : "f"(x), "f"(y)); return r;
}
__device__ __forceinline__ void upk2(ull v, float& x, float& y) {
    asm("mov.b64 {%0, %1}, %2;" : "=f"(x), "=f"(y) : "l"(v));
}
// Packed f32x2 FMA/MUL — Blackwell FFMA2 path (PTX-only)
__device__ __forceinline__ ull fma2(ull a, ull b, ull c) {
    ull d; asm("fma.rn.f32x2 %0, %1, %2, %3;" : "=l"(d) : "l"(a), "l"(b), "l"(c)); return d;
}
__device__ __forceinline__ ull mul2(ull a, ull b) {
    ull d; asm("mul.rn.f32x2 %0, %1, %2;" : "=l"(d) : "l"(a), "l"(b)); return d;
}
__device__ __forceinline__ float sqrt_ap(float x) {
    float r; asm("sqrt.approx.f32 %0, %1;" : "=f"(r) : "f"(x)); return r;
}
__device__ __forceinline__ float actf(float p) {
    return 0.5f * (p + sqrt_ap(fmaf(p, p, 1.0f)));
}
__device__ __forceinline__ ull mk_policy() {
    ull pol;
    asm("createpolicy.fractional.L2::evict_last.b64 %0, 1.0;" : "=l"(pol));
    return pol;
}
__device__ __forceinline__ ull ldg_el(const float* p, ull pol) {
    ull v;
    asm("ld.global.L2::cache_hint.b64 %0, [%1], %2;"
        : "=l"(v) : "l"(p), "l"(pol));
    return v;
}
__device__ __forceinline__ void stg_el(float* p, ull v, ull pol) {
    asm volatile("st.global.L2::cache_hint.b64 [%0], %1, %2;"
                 :: "l"(p), "l"(v), "l"(pol));
}
__device__ __forceinline__ void stg_cs(float* p, ull v) {
    asm volatile("st.global.cs.b64 [%0], %1;" :: "l"(p), "l"(v));
}

// ---------------------------------------------------------------------------
// One-time: pack trig table. angles: [DEPTH][8][512], 512 = blk*8 + a
// ---------------------------------------------------------------------------
__global__ void trig_kernel(const float* __restrict__ angles) {
    int i = blockIdx.x * blockDim.x + threadIdx.x;
    if (i >= DEPTH * 8 * 512) return;
    int m = i / 4096, r = i % 4096;
    int L = r / 512,  q = r % 512;
    int blk = q / 8,  a = q % 8;
    float sn, cs;
    sincosf(angles[i], &sn, &cs);
    g_cs[(m * BLOCKS + blk) * 64 + L * 8 + a] =
        make_ulonglong2(pk2(cs, cs), pk2(sn, sn));
}

// ---------------------------------------------------------------------------
// One-time: dead-write masks via reverse sweep over indices.
// Single CTA of 1024 threads; mark[r]=1 iff row r read by a module > m.
// (Rows >= 4608 are never read back: last module's act goes straight to d_out.)
// ---------------------------------------------------------------------------
__global__ void alive_kernel(const int* __restrict__ indices) {
    __shared__ unsigned char mark[TOTAL];
    const int t = threadIdx.x;
    #pragma unroll
    for (int i = t; i < TOTAL; i += 1024) mark[i] = 0;
    __syncthreads();
    mark[indices[7 * 1024 + t]] = 1;          // reads of the last module
    __syncthreads();
    for (int m = DEPTH - 2; m >= 0; m--) {
        g_alive_sc[m][t] = mark[indices[m * 1024 + t]];
        if (t < 512) g_alive_act[m][t] = mark[IN_W + GROW * m + t];
        __syncthreads();
        if (m > 0) {
            mark[indices[m * 1024 + t]] = 1;
            __syncthreads();
        }
    }
}

// ---------------------------------------------------------------------------
// One butterfly module. CUDA block = (butterfly blk) x (256 batch cols).
// Thread owns 2 batch columns of all 16 rows as f32x2; transform in registers.
// occ-7 cap (72 regs) -> all 1024 CTAs resident in ONE wave (no tail).
// MODE: 0 = middle, 1 = first (gather input*scales), 2 = last (act -> d_out)
// ---------------------------------------------------------------------------
template<int MODE>
__global__ __launch_bounds__(128, 7)
void module_kernel(const float* __restrict__ biases,  // [512] this module
                   const int*   __restrict__ idx,     // [1024] this module
                   int mod,
                   const float* __restrict__ input,   // (1024,4096) for FIRST
                   const float* __restrict__ scales,  // (1024,)     for FIRST
                   float* __restrict__ out_ext)       // d_out for LAST
{
    const int blk = blockIdx.y;
    const int tid = threadIdx.x;

    __shared__ int   s_idx[16];
    __shared__ ull   s_scl[16];
    __shared__ float s_bias[NACT];
    __shared__ unsigned char s_alsc[16];
    __shared__ unsigned char s_alact[NACT];
    __shared__ __align__(16) ulonglong2 s_cs[64];

    if (tid < 16) {
        int row = idx[blk * 16 + tid];
        s_idx[tid]  = row;
        s_alsc[tid] = (MODE == 2) ? 0 : g_alive_sc[mod][blk * 16 + tid];
        if (MODE == 1) { float s = scales[row]; s_scl[tid] = pk2(s, s); }
    }
    if (tid < 8) {
        s_bias[tid]  = biases[blk * 8 + tid];
        s_alact[tid] = (MODE == 2) ? 1 : g_alive_act[mod][blk * NACT + tid];
    }
    if (tid < 64) s_cs[tid] = g_cs[(mod * BLOCKS + blk) * 64 + tid];
    __syncthreads();

    const int b = (blockIdx.x * 128 + tid) * 2;   // first of 2 batch cols
    const ull SGN = 0x8000000080000000ULL;
    const ull pol = mk_policy();

    // Gather 16 rows (16 independent LDG.64 -> MLP=16)
    ull v[16];
    #pragma unroll
    for (int j = 0; j < 16; j++) {
        if (MODE == 1)
            v[j] = *(const ull*)(input + (size_t)s_idx[j] * BATCH + b);
        else
            v[j] = ldg_el(g_data + (size_t)s_idx[j] * BATCH + b, pol);
    }
    if (MODE == 1) {
        #pragma unroll
        for (int j = 0; j < 16; j++) v[j] = mul2(v[j], s_scl[j]);
    }

    // 4 IN rotation layers (strides 1,2,4,8), all in registers
    #pragma unroll
    for (int k = 0; k < 4; k++) {
        const int st = 1 << k;
        #pragma unroll
        for (int g = 0; g < 16; g += 2 * st) {
            #pragma unroll
            for (int j = 0; j < st; j++) {
                const int lo = g + j, hi = lo + st;
                const ulonglong2 cs = s_cs[k * 8 + (g >> 1) + j];  // LDS.128
                const ull ns = cs.y ^ SGN;                         // -s on ALU
                ull xl = v[lo], xh = v[hi];
                v[lo] = fma2(cs.x, xl, mul2(cs.y, xh));
                v[hi] = fma2(ns,   xl, mul2(cs.x, xh));
            }
        }
    }

    // Activation on rows 0..7; write live act rows (d_out for last module)
    #pragma unroll
    for (int u = 0; u < NACT; u++) {
        const float bb = s_bias[u];
        float x0, x1;
        upk2(v[u], x0, x1);
        x0 = actf(x0 + bb); x1 = actf(x1 + bb);
        v[u] = pk2(x0, x1);
        if (MODE == 2)
            stg_cs(out_ext + (size_t)(blk * NACT + u) * BATCH + b, v[u]);
        else if (s_alact[u])
            stg_el(g_data + (size_t)(IN_W + GROW * mod + blk * NACT + u) * BATCH + b,
                   v[u], pol);
    }

    if (MODE != 2) {
        // 4 OUT rotation layers (trig layers 4..7, strides 1,2,4,8)
        #pragma unroll
        for (int k = 0; k < 4; k++) {
            const int st = 1 << k;
            #pragma unroll
            for (int g = 0; g < 16; g += 2 * st) {
                #pragma unroll
                for (int j = 0; j < st; j++) {
                    const int lo = g + j, hi = lo + st;
                    const ulonglong2 cs = s_cs[(4 + k) * 8 + (g >> 1) + j];
                    const ull ns = cs.y ^ SGN;
                    ull xl = v[lo], xh = v[hi];
                    v[lo] = fma2(cs.x, xl, mul2(cs.y, xh));
                    v[hi] = fma2(ns,   xl, mul2(cs.x, xh));
                }
            }
        }
        // Scatter back only live rows (warp-uniform predicate -> cheap)
        #pragma unroll
        for (int j = 0; j < 16; j++)
            if (s_alsc[j])
                stg_el(g_data + (size_t)s_idx[j] * BATCH + b, v[j], pol);
    }
}

// ---------------------------------------------------------------------------
extern "C" void kernel_launch(void* const* d_in, const int* in_sizes, int n_in,
                              void* d_out, int out_size) {
    const float* input   = (const float*)d_in[0];   // (1024, 4096)
    const float* scales  = (const float*)d_in[1];   // (1024,)
    const float* angles  = (const float*)d_in[2];   // (8, 8, 512)
    const float* biases  = (const float*)d_in[3];   // (8, 512)
    const int*   indices = (const int*)d_in[4];     // (8, 1024)
    float* out = (float*)d_out;                     // (512, 4096)

    const int nt = DEPTH * 8 * 512;
    trig_kernel<<<(nt + 255) / 256, 256>>>(angles);
    alive_kernel<<<1, 1024>>>(indices);

    dim3 grid(BATCH / (128 * 2), BLOCKS);   // (16, 64) = 1024 CTAs, one wave
    for (int m = 0; m < DEPTH; m++) {
        const float* bia = biases + (size_t)m * 512;
        const int*   ix  = indices + (size_t)m * 1024;
        if (m == 0)
            module_kernel<1><<<grid, 128>>>(bia, ix, m, input, scales, nullptr);
        else if (m < DEPTH - 1)
            module_kernel<0><<<grid, 128>>>(bia, ix, m, nullptr, nullptr, nullptr);
        else
            module_kernel<2><<<grid, 128>>>(bia, ix, m, nullptr, nullptr, out);
    }
}

// round 11
// speedup vs baseline: 1.3628x; 1.0503x over previous
#include <cuda_runtime.h>

#define BATCH   4096
#define IN_W    1024
#define DEPTH   8
#define BLOCKS  64
#define NACT    8
#define GROW    512
#define TOTAL   5120
#define OUT_W   512

// 84 MB scratch state (static __device__ global: allowed, no runtime alloc)
__device__ float g_data[(size_t)TOTAL * BATCH];

typedef unsigned long long ull;

// Pre-packed rotation constants: g_cs[(m*64+blk)*64 + L*8 + a] = ((c,c),(s,s))
__device__ ulonglong2 g_cs[DEPTH * BLOCKS * 64];

// Liveness masks: alive_sc[m][i] = row idx[m][i] is read by a later module;
// alive_act[m][u] = act row IN_W+512m+u is read by a later module. (m = 0..6)
__device__ unsigned char g_alive_sc[DEPTH - 1][1024];
__device__ unsigned char g_alive_act[DEPTH - 1][512];

__device__ __forceinline__ ull pk2(float x, float y) {
    ull r; asm("mov.b64 %0, {%1, %2};" : "=l"(r) : "f"(x), "f"(y)); return r;
}
__device__ __forceinline__ void upk2(ull v, float& x, float& y) {
    asm("mov.b64 {%0, %1}, %2;" : "=f"(x), "=f"(y) : "l"(v));
}
// Packed f32x2 FMA/MUL — Blackwell FFMA2 path (PTX-only)
__device__ __forceinline__ ull fma2(ull a, ull b, ull c) {
    ull d; asm("fma.rn.f32x2 %0, %1, %2, %3;" : "=l"(d) : "l"(a), "l"(b), "l"(c)); return d;
}
__device__ __forceinline__ ull mul2(ull a, ull b) {
    ull d; asm("mul.rn.f32x2 %0, %1, %2;" : "=l"(d) : "l"(a), "l"(b)); return d;
}
__device__ __forceinline__ float sqrt_ap(float x) {
    float r; asm("sqrt.approx.f32 %0, %1;" : "=f"(r) : "f"(x)); return r;
}
__device__ __forceinline__ float actf(float p) {
    return 0.5f * (p + sqrt_ap(fmaf(p, p, 1.0f)));
}
__device__ __forceinline__ ull mk_keep() {     // evict_last: row re-read later
    ull pol;
    asm("createpolicy.fractional.L2::evict_last.b64 %0, 1.0;" : "=l"(pol));
    return pol;
}
__device__ __forceinline__ ull mk_stream() {   // evict_first: last use
    ull pol;
    asm("createpolicy.fractional.L2::evict_first.b64 %0, 1.0;" : "=l"(pol));
    return pol;
}
__device__ __forceinline__ ull ldg_pol(const float* p, ull pol) {
    ull v;
    asm("ld.global.L2::cache_hint.b64 %0, [%1], %2;"
        : "=l"(v) : "l"(p), "l"(pol));
    return v;
}
__device__ __forceinline__ void stg_pol(float* p, ull v, ull pol) {
    asm volatile("st.global.L2::cache_hint.b64 [%0], %1, %2;"
                 :: "l"(p), "l"(v), "l"(pol));
}
__device__ __forceinline__ void stg_cs(float* p, ull v) {
    asm volatile("st.global.cs.b64 [%0], %1;" :: "l"(p), "l"(v));
}

// ---------------------------------------------------------------------------
// One-time: pack trig table. angles: [DEPTH][8][512], 512 = blk*8 + a
// ---------------------------------------------------------------------------
__global__ void trig_kernel(const float* __restrict__ angles) {
    int i = blockIdx.x * blockDim.x + threadIdx.x;
    if (i >= DEPTH * 8 * 512) return;
    int m = i / 4096, r = i % 4096;
    int L = r / 512,  q = r % 512;
    int blk = q / 8,  a = q % 8;
    float sn, cs;
    sincosf(angles[i], &sn, &cs);
    g_cs[(m * BLOCKS + blk) * 64 + L * 8 + a] =
        make_ulonglong2(pk2(cs, cs), pk2(sn, sn));
}

// ---------------------------------------------------------------------------
// One-time: liveness masks via reverse sweep over indices.
// mark[r]=1 iff row r is read by a module > m.
// ---------------------------------------------------------------------------
__global__ void alive_kernel(const int* __restrict__ indices) {
    __shared__ unsigned char mark[TOTAL];
    const int t = threadIdx.x;
    #pragma unroll
    for (int i = t; i < TOTAL; i += 1024) mark[i] = 0;
    __syncthreads();
    mark[indices[7 * 1024 + t]] = 1;          // reads of the last module
    __syncthreads();
    for (int m = DEPTH - 2; m >= 0; m--) {
        g_alive_sc[m][t] = mark[indices[m * 1024 + t]];
        if (t < 512) g_alive_act[m][t] = mark[IN_W + GROW * m + t];
        __syncthreads();
        if (m > 0) {
            mark[indices[m * 1024 + t]] = 1;
            __syncthreads();
        }
    }
}

// ---------------------------------------------------------------------------
// One butterfly module. CUDA block = (butterfly blk) x (256 batch cols).
// Thread owns 2 batch columns of all 16 rows as f32x2; transform in registers.
// occ-7 cap (72 regs) -> all 1024 CTAs resident in ONE wave.
// Modules 1..7 are PDL-launched: prologue runs before griddepsync; g_data
// is only touched after the sync.
// MODE: 0 = middle, 1 = first (gather input*scales), 2 = last (act -> d_out)
// ---------------------------------------------------------------------------
template<int MODE>
__global__ __launch_bounds__(128, 7)
void module_kernel(const float* __restrict__ biases,  // [512] this module
                   const int*   __restrict__ idx,     // [1024] this module
                   int mod,
                   const float* __restrict__ input,   // (1024,4096) for FIRST
                   const float* __restrict__ scales,  // (1024,)     for FIRST
                   float* __restrict__ out_ext)       // d_out for LAST
{
    const int blk = blockIdx.y;
    const int tid = threadIdx.x;

    __shared__ int   s_idx[16];
    __shared__ ull   s_scl[16];
    __shared__ float s_bias[NACT];
    __shared__ unsigned char s_alsc[16];
    __shared__ unsigned char s_alact[NACT];
    __shared__ __align__(16) ulonglong2 s_cs[64];

    // ---- PDL prologue: reads only pre-finalized tables, no g_data ----
    if (tid < 16) {
        int row = idx[blk * 16 + tid];
        s_idx[tid]  = row;
        s_alsc[tid] = (MODE == 2) ? 0 : g_alive_sc[mod][blk * 16 + tid];
        if (MODE == 1) { float s = scales[row]; s_scl[tid] = pk2(s, s); }
    }
    if (tid < 8) {
        s_bias[tid]  = biases[blk * 8 + tid];
        s_alact[tid] = (MODE == 2) ? 1 : g_alive_act[mod][blk * NACT + tid];
    }
    if (tid < 64) s_cs[tid] = g_cs[(mod * BLOCKS + blk) * 64 + tid];
    __syncthreads();

    const int b = (blockIdx.x * 128 + tid) * 2;   // first of 2 batch cols
    const ull SGN = 0x8000000080000000ULL;
    const ull pk  = mk_keep();
    const ull ps  = mk_stream();

    // ---- wait for previous module's stores to be visible ----
    if (MODE != 1) cudaGridDependencySynchronize();

    // Gather 16 rows (16 independent LDG.64 -> MLP=16). Last-use rows get
    // evict_first (they are also never scattered back).
    ull v[16];
    #pragma unroll
    for (int j = 0; j < 16; j++) {
        if (MODE == 1)
            v[j] = *(const ull*)(input + (size_t)s_idx[j] * BATCH + b);
        else
            v[j] = ldg_pol(g_data + (size_t)s_idx[j] * BATCH + b,
                           s_alsc[j] ? pk : ps);
    }
    if (MODE == 1) {
        #pragma unroll
        for (int j = 0; j < 16; j++) v[j] = mul2(v[j], s_scl[j]);
    }

    // 4 IN rotation layers (strides 1,2,4,8), all in registers
    #pragma unroll
    for (int k = 0; k < 4; k++) {
        const int st = 1 << k;
        #pragma unroll
        for (int g = 0; g < 16; g += 2 * st) {
            #pragma unroll
            for (int j = 0; j < st; j++) {
                const int lo = g + j, hi = lo + st;
                const ulonglong2 cs = s_cs[k * 8 + (g >> 1) + j];  // LDS.128
                const ull ns = cs.y ^ SGN;                         // -s on ALU
                ull xl = v[lo], xh = v[hi];
                v[lo] = fma2(cs.x, xl, mul2(cs.y, xh));
                v[hi] = fma2(ns,   xl, mul2(cs.x, xh));
            }
        }
    }

    // Activation on rows 0..7; write live act rows (d_out for last module)
    #pragma unroll
    for (int u = 0; u < NACT; u++) {
        const float bb = s_bias[u];
        float x0, x1;
        upk2(v[u], x0, x1);
        x0 = actf(x0 + bb); x1 = actf(x1 + bb);
        v[u] = pk2(x0, x1);
        if (MODE == 2)
            stg_cs(out_ext + (size_t)(blk * NACT + u) * BATCH + b, v[u]);
        else if (s_alact[u])
            stg_pol(g_data + (size_t)(IN_W + GROW * mod + blk * NACT + u) * BATCH + b,
                    v[u], pk);
    }

    if (MODE != 2) {
        // 4 OUT rotation layers (trig layers 4..7, strides 1,2,4,8)
        #pragma unroll
        for (int k = 0; k < 4; k++) {
            const int st = 1 << k;
            #pragma unroll
            for (int g = 0; g < 16; g += 2 * st) {
                #pragma unroll
                for (int j = 0; j < st; j++) {
                    const int lo = g + j, hi = lo + st;
                    const ulonglong2 cs = s_cs[(4 + k) * 8 + (g >> 1) + j];
                    const ull ns = cs.y ^ SGN;
                    ull xl = v[lo], xh = v[hi];
                    v[lo] = fma2(cs.x, xl, mul2(cs.y, xh));
                    v[hi] = fma2(ns,   xl, mul2(cs.x, xh));
                }
            }
        }
        // Scatter back only live rows (warp-uniform predicate)
        #pragma unroll
        for (int j = 0; j < 16; j++)
            if (s_alsc[j])
                stg_pol(g_data + (size_t)s_idx[j] * BATCH + b, v[j], pk);
    }

    // Allow the next PDL kernel to launch as soon as our work is done.
    cudaTriggerProgrammaticLaunchCompletion();
}

// ---------------------------------------------------------------------------
extern "C" void kernel_launch(void* const* d_in, const int* in_sizes, int n_in,
                              void* d_out, int out_size) {
    const float* input   = (const float*)d_in[0];   // (1024, 4096)
    const float* scales  = (const float*)d_in[1];   // (1024,)
    const float* angles  = (const float*)d_in[2];   // (8, 8, 512)
    const float* biases  = (const float*)d_in[3];   // (8, 512)
    const int*   indices = (const int*)d_in[4];     // (8, 1024)
    float* out = (float*)d_out;                     // (512, 4096)

    const int nt = DEPTH * 8 * 512;
    trig_kernel<<<(nt + 255) / 256, 256>>>(angles);
    alive_kernel<<<1, 1024>>>(indices);

    dim3 grid(BATCH / (128 * 2), BLOCKS);   // (16, 64) = 1024 CTAs, one wave

    // Module 0: normal launch (must wait for trig/alive prep anyway).
    module_kernel<1><<<grid, 128>>>(biases, indices, 0, input, scales, nullptr);

    // Modules 1..7: PDL — overlap each launch/prologue with the previous tail.
    for (int m = 1; m < DEPTH; m++) {
        const float* bia = biases + (size_t)m * 512;
        const int*   ix  = indices + (size_t)m * 1024;

        cudaLaunchConfig_t cfg = {};
        cfg.gridDim  = grid;
        cfg.blockDim = dim3(128, 1, 1);
        cfg.dynamicSmemBytes = 0;
        cfg.stream = 0;
        cudaLaunchAttribute at[1];
        at[0].id = cudaLaunchAttributeProgrammaticStreamSerialization;
        at[0].val.programmaticStreamSerializationAllowed = 1;
        cfg.attrs = at;
        cfg.numAttrs = 1;

        if (m < DEPTH - 1)
            cudaLaunchKernelEx(&cfg, module_kernel<0>, bia, ix, m,
                               (const float*)nullptr, (const float*)nullptr,
                               (float*)nullptr);
        else
            cudaLaunchKernelEx(&cfg, module_kernel<2>, bia, ix, m,
                               (const float*)nullptr, (const float*)nullptr,
                               out);
    }
}